// round 7
// baseline (speedup 1.0000x reference)
#include <cuda_runtime.h>
#include <cuda_bf16.h>
#include <cstdint>

// ---------------------------------------------------------------------------
// DeepTransitionRNN: T=512, B=128, D=256, H=256, L=4
//
// Plan:
//  1) memset(out, 0)                         (masked steps stay zero)
//  2) xproj_kernel: XP[t][m][hc][b] = x[t,b,:] @ Wm[:,hc] for the 5 x-side
//     matrices m in {Wr_x, Wz_x, Wl_x, Cx, Wt}  (one big fp32 GEMM, f32x2)
//  3) rnn_kernel: persistent, 128 CTAs = 4 groups (32 batch rows) x 32 CTAs
//     (8 H-columns each). All 16 h-side weight slices live in SMEM (128KB).
//     5 GEMM phases/step, h exchanged via ping-pong L2 buffer + sense-
//     reversing group barrier.
// ---------------------------------------------------------------------------

#define T_STEPS 512
#define BATCH   128
#define DDIM    256
#define HDIM    256
#define NLAYERS 4
#define NMAT    16          // 4 (phase A) + 4 layers * 3
#define GROUPS  4
#define RPG     32          // batch rows per group
#define CPC     8           // H columns per CTA
#define CPG     32          // CTAs per group
#define XP_MS   (HDIM*BATCH)  // stride between matrices in XP (32768 floats)

typedef unsigned long long ull;

// ---- device scratch (static globals: allocation-free) ----------------------
__device__ __align__(16) float g_XP[(size_t)T_STEPS * 5 * HDIM * BATCH]; // 335 MB
__device__ __align__(16) float g_Hbuf[2][GROUPS][HDIM * RPG];
__device__ unsigned g_arrive[GROUPS];
__device__ unsigned g_release[GROUPS];

// ---- fast, accurate activations (error ~1e-7, well under 1e-3) -------------
__device__ __forceinline__ float sigmoidf_(float x) {
    x = fminf(fmaxf(x, -30.f), 30.f);
    return 1.f / (1.f + __expf(-x));
}
__device__ __forceinline__ float tanhf_(float x) {
    x = fminf(fmaxf(x, -15.f), 15.f);
    float e = __expf(2.f * x);
    return (e - 1.f) / (e + 1.f);
}

// ---------------------------------------------------------------------------
// Kernel 1: x-projection GEMM.
// C[M=65536, N=1280] = x[M, 256] @ Wcat[256, 1280], stored as
// g_XP[((t*5+mat)*256 + hc)*128 + b].
// Tile 64(M) x 64(N); since 128 % 64 == 0 each tile sits in a single t and a
// single source matrix. 256 threads, 4x4 microtile, packed f32x2 FMAs,
// smem-transposed epilogue so global stores are b-contiguous float4s.
// ---------------------------------------------------------------------------
__global__ void __launch_bounds__(256) xproj_kernel(
    const float* __restrict__ x,
    const float* __restrict__ Wr, const float* __restrict__ Wz,
    const float* __restrict__ Wl, const float* __restrict__ Cx,
    const float* __restrict__ Wt)
{
    __shared__ float AsmT[16 * 68];   // [k][m], padded
    __shared__ float Bsm [16 * 68];   // [k][n], padded
    __shared__ float Csm [64 * 68];   // [n][m], padded

    const int tid   = threadIdx.x;
    const int bn    = blockIdx.x;            // 0..19  (N tiles)
    const int bm    = blockIdx.y;            // 0..1023 (M tiles)
    const int t     = bm >> 1;
    const int brow0 = (bm & 1) * 64;
    const int n0    = bn * 64;
    const int mat   = n0 >> 8;                // 0..4
    const int hc0   = n0 & 255;
    const float* Wsrc = (mat == 0) ? Wr : (mat == 1) ? Wz :
                        (mat == 2) ? Wl : (mat == 3) ? Cx : Wt;
    // NOTE: for Wr/Wz/Wl the x-part is rows [0,256) (cat = [xt, h]); stride
    // is HDIM=256 for all five matrices, so base pointers work directly.

    const int ty = tid >> 4;      // 0..15 (M quads)
    const int tx = tid & 15;      // 0..15 (N quads)

    ull acc[4][2];
    #pragma unroll
    for (int i = 0; i < 4; ++i) { acc[i][0] = 0ull; acc[i][1] = 0ull; }

    const int a_m = tid >> 2;            // 0..63
    const int a_k = (tid & 3) * 4;       // 0,4,8,12
    const int b_k = tid >> 4;            // 0..15
    const int b_c = (tid & 15) * 4;      // 0..60

    const float* ag = x + ((size_t)(t * BATCH + brow0 + a_m)) * DDIM + a_k;
    const float* bg = Wsrc + (size_t)b_k * HDIM + hc0 + b_c;

    for (int k0 = 0; k0 < DDIM; k0 += 16) {
        float4 av = *(const float4*)(ag + k0);
        AsmT[(a_k + 0) * 68 + a_m] = av.x;
        AsmT[(a_k + 1) * 68 + a_m] = av.y;
        AsmT[(a_k + 2) * 68 + a_m] = av.z;
        AsmT[(a_k + 3) * 68 + a_m] = av.w;
        float4 bv = *(const float4*)(bg + (size_t)k0 * HDIM);
        *(float4*)&Bsm[b_k * 68 + b_c] = bv;
        __syncthreads();

        #pragma unroll
        for (int k = 0; k < 16; ++k) {
            float4 a4 = *(const float4*)&AsmT[k * 68 + ty * 4];
            ulonglong2 wv = *(const ulonglong2*)&Bsm[k * 68 + tx * 4];
            ull a2;
            #define XPROJ_STEP(i, comp)                                          \
                asm("mov.b64 %0,{%1,%1};" : "=l"(a2) : "f"(comp));               \
                asm("fma.rn.f32x2 %0,%1,%2,%0;" : "+l"(acc[i][0])                \
                    : "l"(a2), "l"(wv.x));                                       \
                asm("fma.rn.f32x2 %0,%1,%2,%0;" : "+l"(acc[i][1])                \
                    : "l"(a2), "l"(wv.y));
            XPROJ_STEP(0, a4.x)
            XPROJ_STEP(1, a4.y)
            XPROJ_STEP(2, a4.z)
            XPROJ_STEP(3, a4.w)
            #undef XPROJ_STEP
        }
        __syncthreads();
    }

    // epilogue: transpose through Csm so global stores are b-contiguous
    #pragma unroll
    for (int i = 0; i < 4; ++i) {
        float c0, c1, c2, c3;
        asm("mov.b64 {%0,%1},%2;" : "=f"(c0), "=f"(c1) : "l"(acc[i][0]));
        asm("mov.b64 {%0,%1},%2;" : "=f"(c2), "=f"(c3) : "l"(acc[i][1]));
        Csm[(tx * 4 + 0) * 68 + ty * 4 + i] = c0;
        Csm[(tx * 4 + 1) * 68 + ty * 4 + i] = c1;
        Csm[(tx * 4 + 2) * 68 + ty * 4 + i] = c2;
        Csm[(tx * 4 + 3) * 68 + ty * 4 + i] = c3;
    }
    __syncthreads();

    const int nl = tid >> 2;        // 0..63 local N index
    const int mq = tid & 3;         // quarter of the 64 M values
    float* dst = g_XP + ((size_t)((t * 5 + mat) * HDIM + hc0 + nl)) * BATCH
                 + brow0 + mq * 16;
    #pragma unroll
    for (int q = 0; q < 4; ++q) {
        float4 v = *(const float4*)&Csm[nl * 68 + mq * 16 + q * 4];
        *(float4*)(dst + q * 4) = v;
    }
}

// ---------------------------------------------------------------------------
// Recurrence kernel helpers
// ---------------------------------------------------------------------------
__device__ __forceinline__ void group_barrier(int g, unsigned& sense, int tid) {
    __threadfence();          // make this thread's Hbuf stores visible
    __syncthreads();          // all threads of CTA done writing
    if (tid == 0) {
        unsigned s = sense ^ 1u;
        sense = s;
        if (atomicAdd(&g_arrive[g], 1u) == (unsigned)(CPG - 1)) {
            atomicExch(&g_arrive[g], 0u);   // reset BEFORE release
            __threadfence();
            atomicExch(&g_release[g], s);
        } else {
            while (*((volatile unsigned*)&g_release[g]) != s) { }
        }
        __threadfence();
    } else {
        sense ^= 1u;   // keep per-thread copies consistent (unused elsewhere)
    }
    __syncthreads();
}

// reload full group h (256 x 32 floats) from L2 buffer into smem (L1 bypass!)
__device__ __forceinline__ void reload_hT(float* hT, const float* hb, int tid) {
    #pragma unroll
    for (int i = 0; i < 8; ++i) {
        int idx = tid * 4 + i * 1024;
        float4 v = __ldcg((const float4*)(hb + idx));
        *(float4*)(hT + idx) = v;
    }
}

// one warp computes a 32-row x 4-col slice of (h @ W) using packed f32x2 FMAs
__device__ __forceinline__ void gemm_slice(const float* __restrict__ hT,
                                           const float* __restrict__ wp,
                                           float* __restrict__ gout, int lane) {
    ull acc0 = 0ull, acc1 = 0ull;
    #pragma unroll 8
    for (int k = 0; k < HDIM; ++k) {
        float a = hT[k * 32 + lane];                       // conflict-free
        ulonglong2 wv = *(const ulonglong2*)(wp + k * CPC); // broadcast LDS.128
        ull a2;
        asm("mov.b64 %0,{%1,%1};" : "=l"(a2) : "f"(a));
        asm("fma.rn.f32x2 %0,%1,%2,%0;" : "+l"(acc0) : "l"(a2), "l"(wv.x));
        asm("fma.rn.f32x2 %0,%1,%2,%0;" : "+l"(acc1) : "l"(a2), "l"(wv.y));
    }
    float o0, o1, o2, o3;
    asm("mov.b64 {%0,%1},%2;" : "=f"(o0), "=f"(o1) : "l"(acc0));
    asm("mov.b64 {%0,%1},%2;" : "=f"(o2), "=f"(o3) : "l"(acc1));
    gout[0]  = o0;
    gout[32] = o1;
    gout[64] = o2;
    gout[96] = o3;
}

// ---------------------------------------------------------------------------
// Kernel 2: the recurrence. 128 CTAs x 256 threads, persistent.
// Dynamic smem: Wsm 16x256x8 (128KB) | hT 256x32 (32KB) | Gsm 4x8x32 (4KB)
// ---------------------------------------------------------------------------
#define SMEM_FLOATS (NMAT*HDIM*CPC + HDIM*RPG + 4*CPC*RPG)
#define SMEM_BYTES  (SMEM_FLOATS * 4)

__global__ void __launch_bounds__(256, 1) rnn_kernel(
    const float* __restrict__ Wr, const float* __restrict__ Wz,
    const float* __restrict__ Wl, const float* __restrict__ Ch,
    const float* __restrict__ Tr, const float* __restrict__ Tz,
    const float* __restrict__ Tn,
    const int*   __restrict__ lengths,
    float*       __restrict__ out)
{
    extern __shared__ float smem[];
    float* Wsm = smem;                                // 32768 floats
    float* hT  = smem + NMAT * HDIM * CPC;            //  8192 floats
    float* Gsm = smem + NMAT * HDIM * CPC + HDIM*RPG; //  1024 floats

    const int tid  = threadIdx.x;
    const int cta  = blockIdx.x;
    const int g    = cta >> 5;        // group 0..3
    const int cb   = cta & 31;        // column block within group
    const int col0 = cb * CPC;

    // ---- load this CTA's 8-column slice of all 16 h-side matrices ----------
    for (int idx = tid; idx < NMAT * HDIM * CPC; idx += 256) {
        int m = idx >> 11;
        int k = (idx >> 3) & 255;
        int c = idx & 7;
        const float* src;
        if (m == 0)      src = Wr + (size_t)(DDIM + k) * HDIM;   // h-part rows
        else if (m == 1) src = Wz + (size_t)(DDIM + k) * HDIM;
        else if (m == 2) src = Wl + (size_t)(DDIM + k) * HDIM;
        else if (m == 3) src = Ch + (size_t)k * HDIM;
        else {
            int mm = m - 4, layer = mm / 3, which = mm % 3;
            const float* base = (which == 0) ? Tr : (which == 1) ? Tz : Tn;
            src = base + (size_t)layer * HDIM * HDIM + (size_t)k * HDIM;
        }
        Wsm[idx] = src[col0 + c];
    }
    for (int idx = tid; idx < HDIM * RPG; idx += 256) hT[idx] = 0.f;

    // ---- per-thread elementwise identity ------------------------------------
    const int r    = tid & 31;        // batch row within group
    const int cl   = tid >> 5;        // local column 0..7
    const int b    = g * RPG + r;     // global batch index
    const int colg = col0 + cl;       // global H column
    const int mylen = lengths[b];
    const int Lg    = lengths[g * RPG];  // group max (sorted descending)

    const int w    = tid >> 5;
    const int lane = tid & 31;

    unsigned sense = 0;
    if (tid == 0) sense = *((volatile unsigned*)&g_release[g]);
    __syncthreads();

    int pp = 0;
    float* hb0 = &g_Hbuf[0][g][0];
    float* hb1 = &g_Hbuf[1][g][0];

    for (int t = 0; t < Lg; ++t) {
        const bool act = (t < mylen);
        const float hold = hT[colg * 32 + r];   // real h at step start

        // ================= phase A: 4 GEMMs on h =================
        {
            int m = w >> 1, ch = w & 1;
            const float* wp = Wsm + (m * HDIM) * CPC + ch * 4;
            float* gout = Gsm + (m * CPC + ch * 4) * 32 + lane;
            gemm_slice(hT, wp, gout, lane);
        }
        __syncthreads();
        {
            const float* xp = g_XP + ((size_t)(t * 5) * HDIM + colg) * BATCH + b;
            float xr = xp[0 * XP_MS];
            float xz = xp[1 * XP_MS];
            float xl = xp[2 * XP_MS];
            float xc = xp[3 * XP_MS];
            float xw = xp[4 * XP_MS];
            float gr  = Gsm[(0 * CPC + cl) * 32 + r];
            float gz  = Gsm[(1 * CPC + cl) * 32 + r];
            float gl  = Gsm[(2 * CPC + cl) * 32 + r];
            float gch = Gsm[(3 * CPC + cl) * 32 + r];
            float rv = sigmoidf_(xr + gr);
            float zv = sigmoidf_(xz + gz);
            float lv = sigmoidf_(xl + gl);
            float nv = tanhf_(xc + rv * gch) + lv * xw;
            float hn = (1.f - zv) * hold + zv * nv;   // candidate (unmasked)
            (pp ? hb1 : hb0)[colg * 32 + r] = hn;
        }
        group_barrier(g, sense, tid);
        reload_hT(hT, pp ? hb1 : hb0, tid);
        pp ^= 1;
        __syncthreads();

        // ================= 4 transition layers =================
        #pragma unroll 1
        for (int layer = 0; layer < NLAYERS; ++layer) {
            if (w < 6) {
                int m = w >> 1, ch = w & 1;
                int mi = 4 + layer * 3 + m;
                const float* wp = Wsm + (mi * HDIM) * CPC + ch * 4;
                float* gout = Gsm + (m * CPC + ch * 4) * 32 + lane;
                gemm_slice(hT, wp, gout, lane);
            }
            __syncthreads();
            {
                float hcur = hT[colg * 32 + r];
                float rr = sigmoidf_(Gsm[(0 * CPC + cl) * 32 + r]);
                float zz = sigmoidf_(Gsm[(1 * CPC + cl) * 32 + r]);
                float nn = tanhf_(rr * Gsm[(2 * CPC + cl) * 32 + r]);
                float hnew = (1.f - zz) * nn + zz * hcur;
                float* hb = pp ? hb1 : hb0;
                if (layer == NLAYERS - 1) {
                    // mask applies once per step, at the end of the cell
                    hb[colg * 32 + r] = act ? hnew : hold;
                    if (act)
                        out[((size_t)t * BATCH + b) * HDIM + colg] = hnew;
                } else {
                    hb[colg * 32 + r] = hnew;
                }
            }
            group_barrier(g, sense, tid);
            reload_hT(hT, pp ? hb1 : hb0, tid);
            pp ^= 1;
            __syncthreads();
        }
    }
}

// ---------------------------------------------------------------------------
// kernel_launch: memset -> x-projection GEMM -> persistent recurrence
// (all on the default stream; graph-capturable, allocation-free)
// ---------------------------------------------------------------------------
extern "C" void kernel_launch(void* const* d_in, const int* in_sizes, int n_in,
                              void* d_out, int out_size)
{
    const float* x       = (const float*)d_in[0];
    const int*   lengths = (const int*)  d_in[1];
    const float* Wr      = (const float*)d_in[2];
    const float* Wz      = (const float*)d_in[3];
    const float* Wl      = (const float*)d_in[4];
    const float* Wt      = (const float*)d_in[5];
    const float* Cx      = (const float*)d_in[6];
    const float* Ch      = (const float*)d_in[7];
    const float* Tr      = (const float*)d_in[8];
    const float* Tz      = (const float*)d_in[9];
    const float* Tn      = (const float*)d_in[10];
    float* out = (float*)d_out;
    (void)in_sizes; (void)n_in;

    cudaMemsetAsync(out, 0, (size_t)out_size * sizeof(float));

    dim3 ggrid(20, 1024);           // N tiles x M tiles
    xproj_kernel<<<ggrid, 256>>>(x, Wr, Wz, Wl, Cx, Wt);

    cudaFuncSetAttribute(rnn_kernel,
                         cudaFuncAttributeMaxDynamicSharedMemorySize,
                         SMEM_BYTES);
    rnn_kernel<<<GROUPS * CPG, 256, SMEM_BYTES>>>(
        Wr, Wz, Wl, Ch, Tr, Tz, Tn, lengths, out);
}

// round 8
// speedup vs baseline: 1.4046x; 1.4046x over previous
#include <cuda_runtime.h>
#include <cuda_bf16.h>
#include <cstdint>

// ---------------------------------------------------------------------------
// DeepTransitionRNN: T=512, B=128, D=256, H=256, L=4
//
//  1) memset(out, 0)
//  2) xproj_kernel: XP[t][m][hc][b] = x[t,b,:] @ Wm[:,hc], m in
//     {Wr_x, Wz_x, Wl_x, Cx, Wt}  (fp32 GEMM, packed f32x2)
//  3) rnn_kernel: persistent, 128 CTAs = 4 groups (32 batch rows) x 32 CTAs
//     (8 H-columns each). All 16 h-side weight slices SMEM-resident (128KB).
//     5 GEMM phases/step; h exchanged via ping-pong L2 buffer; group sync via
//     monotonic per-CTA flag counters (st.release / coalesced acquire-poll).
// ---------------------------------------------------------------------------

#define T_STEPS 512
#define BATCH   128
#define DDIM    256
#define HDIM    256
#define NLAYERS 4
#define NMAT    16
#define GROUPS  4
#define RPG     32          // batch rows per group
#define CPC     8           // H columns per CTA
#define CPG     32          // CTAs per group
#define XP_MS   (HDIM*BATCH)

typedef unsigned long long ull;

// ---- device scratch (static globals: allocation-free) ----------------------
__device__ __align__(16)  float    g_XP[(size_t)T_STEPS * 5 * HDIM * BATCH];
__device__ __align__(16)  float    g_Hbuf[2][GROUPS][HDIM * RPG];
__device__ __align__(128) unsigned g_flag[GROUPS][CPG];   // monotonic counters

// ---- activations (fp32, error ~1e-7) ---------------------------------------
__device__ __forceinline__ float sigmoidf_(float x) {
    x = fminf(fmaxf(x, -30.f), 30.f);
    return 1.f / (1.f + __expf(-x));
}
__device__ __forceinline__ float tanhf_(float x) {
    x = fminf(fmaxf(x, -15.f), 15.f);
    float e = __expf(2.f * x);
    return (e - 1.f) / (e + 1.f);
}

// ---------------------------------------------------------------------------
// Kernel 1: x-projection GEMM (unchanged from passing R7 version).
// ---------------------------------------------------------------------------
__global__ void __launch_bounds__(256) xproj_kernel(
    const float* __restrict__ x,
    const float* __restrict__ Wr, const float* __restrict__ Wz,
    const float* __restrict__ Wl, const float* __restrict__ Cx,
    const float* __restrict__ Wt)
{
    __shared__ float AsmT[16 * 68];
    __shared__ float Bsm [16 * 68];
    __shared__ float Csm [64 * 68];

    const int tid   = threadIdx.x;
    const int bn    = blockIdx.x;
    const int bm    = blockIdx.y;
    const int t     = bm >> 1;
    const int brow0 = (bm & 1) * 64;
    const int n0    = bn * 64;
    const int mat   = n0 >> 8;
    const int hc0   = n0 & 255;
    const float* Wsrc = (mat == 0) ? Wr : (mat == 1) ? Wz :
                        (mat == 2) ? Wl : (mat == 3) ? Cx : Wt;

    const int ty = tid >> 4;
    const int tx = tid & 15;

    ull acc[4][2];
    #pragma unroll
    for (int i = 0; i < 4; ++i) { acc[i][0] = 0ull; acc[i][1] = 0ull; }

    const int a_m = tid >> 2;
    const int a_k = (tid & 3) * 4;
    const int b_k = tid >> 4;
    const int b_c = (tid & 15) * 4;

    const float* ag = x + ((size_t)(t * BATCH + brow0 + a_m)) * DDIM + a_k;
    const float* bg = Wsrc + (size_t)b_k * HDIM + hc0 + b_c;

    for (int k0 = 0; k0 < DDIM; k0 += 16) {
        float4 av = *(const float4*)(ag + k0);
        AsmT[(a_k + 0) * 68 + a_m] = av.x;
        AsmT[(a_k + 1) * 68 + a_m] = av.y;
        AsmT[(a_k + 2) * 68 + a_m] = av.z;
        AsmT[(a_k + 3) * 68 + a_m] = av.w;
        float4 bv = *(const float4*)(bg + (size_t)k0 * HDIM);
        *(float4*)&Bsm[b_k * 68 + b_c] = bv;
        __syncthreads();

        #pragma unroll
        for (int k = 0; k < 16; ++k) {
            float4 a4 = *(const float4*)&AsmT[k * 68 + ty * 4];
            ulonglong2 wv = *(const ulonglong2*)&Bsm[k * 68 + tx * 4];
            ull a2;
            #define XPROJ_STEP(i, comp)                                          \
                asm("mov.b64 %0,{%1,%1};" : "=l"(a2) : "f"(comp));               \
                asm("fma.rn.f32x2 %0,%1,%2,%0;" : "+l"(acc[i][0])                \
                    : "l"(a2), "l"(wv.x));                                       \
                asm("fma.rn.f32x2 %0,%1,%2,%0;" : "+l"(acc[i][1])                \
                    : "l"(a2), "l"(wv.y));
            XPROJ_STEP(0, a4.x)
            XPROJ_STEP(1, a4.y)
            XPROJ_STEP(2, a4.z)
            XPROJ_STEP(3, a4.w)
            #undef XPROJ_STEP
        }
        __syncthreads();
    }

    #pragma unroll
    for (int i = 0; i < 4; ++i) {
        float c0, c1, c2, c3;
        asm("mov.b64 {%0,%1},%2;" : "=f"(c0), "=f"(c1) : "l"(acc[i][0]));
        asm("mov.b64 {%0,%1},%2;" : "=f"(c2), "=f"(c3) : "l"(acc[i][1]));
        Csm[(tx * 4 + 0) * 68 + ty * 4 + i] = c0;
        Csm[(tx * 4 + 1) * 68 + ty * 4 + i] = c1;
        Csm[(tx * 4 + 2) * 68 + ty * 4 + i] = c2;
        Csm[(tx * 4 + 3) * 68 + ty * 4 + i] = c3;
    }
    __syncthreads();

    const int nl = tid >> 2;
    const int mq = tid & 3;
    float* dst = g_XP + ((size_t)((t * 5 + mat) * HDIM + hc0 + nl)) * BATCH
                 + brow0 + mq * 16;
    #pragma unroll
    for (int q = 0; q < 4; ++q) {
        float4 v = *(const float4*)&Csm[nl * 68 + mq * 16 + q * 4];
        *(float4*)(dst + q * 4) = v;
    }
}

// ---------------------------------------------------------------------------
// Recurrence helpers
// ---------------------------------------------------------------------------

// arrive: bar.sync (creates CTA-wide happens-before), then ONE release store.
__device__ __forceinline__ void barrier_arrive(unsigned* flags, int cb,
                                               unsigned target, int tid) {
    __syncthreads();
    if (tid == 0)
        asm volatile("st.release.gpu.global.u32 [%0],%1;"
                     :: "l"(flags + cb), "r"(target) : "memory");
}

// wait: warp 0 polls all 32 group flags (one coalesced 128B load per sweep).
__device__ __forceinline__ void barrier_wait(unsigned* flags,
                                             unsigned target, int tid) {
    if (tid < 32) {
        unsigned v;
        do {
            asm volatile("ld.acquire.gpu.global.u32 %0,[%1];"
                         : "=r"(v) : "l"(flags + tid) : "memory");
        } while (__ballot_sync(0xffffffffu, v < target));
    }
    __syncthreads();
}

// reload full group h (256 x 32 floats) from L2 buffer into smem (L1 bypass)
__device__ __forceinline__ void reload_hT(float* hT, const float* hb, int tid) {
    #pragma unroll
    for (int i = 0; i < 8; ++i) {
        int idx = tid * 4 + i * 1024;
        float4 v = __ldcg((const float4*)(hb + idx));
        *(float4*)(hT + idx) = v;
    }
}

// one warp: 32 rows x 8 cols over HALF the k range (k-split halves the
// accumulator-chain depth and doubles phase-A warp parallelism)
__device__ __forceinline__ void gemm8(const float* __restrict__ hT,
                                      const float* __restrict__ wmat,
                                      float* __restrict__ gout,
                                      int kh, int lane)
{
    ull a0 = 0ull, a1 = 0ull, a2 = 0ull, a3 = 0ull;
    const float* hp = hT + kh * (128 * 32) + lane;
    const float* wp = wmat + kh * (128 * 8);
    #pragma unroll 8
    for (int k = 0; k < 128; ++k) {
        float a = hp[k * 32];                               // conflict-free
        ull ad;
        asm("mov.b64 %0,{%1,%1};" : "=l"(ad) : "f"(a));
        ulonglong2 w01 = *(const ulonglong2*)(wp + k * 8);  // broadcast
        ulonglong2 w23 = *(const ulonglong2*)(wp + k * 8 + 4);
        asm("fma.rn.f32x2 %0,%1,%2,%0;" : "+l"(a0) : "l"(ad), "l"(w01.x));
        asm("fma.rn.f32x2 %0,%1,%2,%0;" : "+l"(a1) : "l"(ad), "l"(w01.y));
        asm("fma.rn.f32x2 %0,%1,%2,%0;" : "+l"(a2) : "l"(ad), "l"(w23.x));
        asm("fma.rn.f32x2 %0,%1,%2,%0;" : "+l"(a3) : "l"(ad), "l"(w23.y));
    }
    float o0, o1, o2, o3, o4, o5, o6, o7;
    asm("mov.b64 {%0,%1},%2;" : "=f"(o0), "=f"(o1) : "l"(a0));
    asm("mov.b64 {%0,%1},%2;" : "=f"(o2), "=f"(o3) : "l"(a1));
    asm("mov.b64 {%0,%1},%2;" : "=f"(o4), "=f"(o5) : "l"(a2));
    asm("mov.b64 {%0,%1},%2;" : "=f"(o6), "=f"(o7) : "l"(a3));
    gout[0 * 32 + lane] = o0;  gout[1 * 32 + lane] = o1;
    gout[2 * 32 + lane] = o2;  gout[3 * 32 + lane] = o3;
    gout[4 * 32 + lane] = o4;  gout[5 * 32 + lane] = o5;
    gout[6 * 32 + lane] = o6;  gout[7 * 32 + lane] = o7;
}

// ---------------------------------------------------------------------------
// Kernel 2: the recurrence. 128 CTAs x 256 threads, persistent.
// Dynamic smem: Wsm 16x256x8 (128KB) | hT 256x32 (32KB) | Gp 2x32x32 (8KB)
// ---------------------------------------------------------------------------
#define SMEM_FLOATS (NMAT*HDIM*CPC + HDIM*RPG + 2*32*RPG)
#define SMEM_BYTES  (SMEM_FLOATS * 4)

__global__ void __launch_bounds__(256, 1) rnn_kernel(
    const float* __restrict__ Wr, const float* __restrict__ Wz,
    const float* __restrict__ Wl, const float* __restrict__ Ch,
    const float* __restrict__ Tr, const float* __restrict__ Tz,
    const float* __restrict__ Tn,
    const int*   __restrict__ lengths,
    float*       __restrict__ out)
{
    extern __shared__ float smem[];
    float* Wsm = smem;                                   // 32768 floats
    float* hT  = smem + NMAT * HDIM * CPC;               //  8192 floats
    float* Gp  = smem + NMAT * HDIM * CPC + HDIM * RPG;  //  2048 floats
    __shared__ unsigned sF0;

    const int tid  = threadIdx.x;
    const int cta  = blockIdx.x;
    const int g    = cta >> 5;
    const int cb   = cta & 31;
    const int col0 = cb * CPC;

    // ---- load this CTA's 8-column slice of all 16 h-side matrices ----------
    for (int idx = tid; idx < NMAT * HDIM * CPC; idx += 256) {
        int m = idx >> 11;
        int k = (idx >> 3) & 255;
        int c = idx & 7;
        const float* src;
        if (m == 0)      src = Wr + (size_t)(DDIM + k) * HDIM;
        else if (m == 1) src = Wz + (size_t)(DDIM + k) * HDIM;
        else if (m == 2) src = Wl + (size_t)(DDIM + k) * HDIM;
        else if (m == 3) src = Ch + (size_t)k * HDIM;
        else {
            int mm = m - 4, layer = mm / 3, which = mm % 3;
            const float* base = (which == 0) ? Tr : (which == 1) ? Tz : Tn;
            src = base + (size_t)layer * HDIM * HDIM + (size_t)k * HDIM;
        }
        Wsm[idx] = src[col0 + c];
    }
    for (int idx = tid; idx < HDIM * RPG; idx += 256) hT[idx] = 0.f;

    const int r    = tid & 31;
    const int cl   = tid >> 5;
    const int b    = g * RPG + r;
    const int colg = col0 + cl;
    const int mylen = lengths[b];
    const int Lg    = lengths[g * RPG];     // sorted descending -> group max

    const int w    = tid >> 5;
    const int lane = tid & 31;
    const int ei   = cl * 32 + r;

    unsigned* flags = &g_flag[g][0];
    if (tid == 0) sF0 = *((volatile unsigned*)(flags + cb));
    __syncthreads();
    unsigned p = sF0;                        // monotonic phase counter base

    int pp = 0;
    float* hb0 = &g_Hbuf[0][g][0];
    float* hb1 = &g_Hbuf[1][g][0];

    for (int t = 0; t < Lg; ++t) {
        const bool act = (t < mylen);

        // prefetch XP for this step (DRAM latency hidden under phase-A GEMM)
        const float* xp = g_XP + ((size_t)(t * 5) * HDIM + colg) * BATCH + b;
        float xr = __ldcg(xp + 0 * XP_MS);
        float xz = __ldcg(xp + 1 * XP_MS);
        float xl = __ldcg(xp + 2 * XP_MS);
        float xc = __ldcg(xp + 3 * XP_MS);
        float xw = __ldcg(xp + 4 * XP_MS);

        const float hold = hT[colg * 32 + r];

        // ================= phase A: 4 GEMMs, 8 warp jobs (mat x k-half) ======
        {
            int mi = w >> 1, kh = w & 1;
            gemm8(hT, Wsm + mi * (HDIM * CPC), Gp + kh * 1024 + mi * 256,
                  kh, lane);
        }
        __syncthreads();
        {
            float gr  = Gp[ei]       + Gp[1024 + ei];
            float gz  = Gp[256 + ei] + Gp[1280 + ei];
            float gl  = Gp[512 + ei] + Gp[1536 + ei];
            float gch = Gp[768 + ei] + Gp[1792 + ei];
            float rv = sigmoidf_(xr + gr);
            float zv = sigmoidf_(xz + gz);
            float lv = sigmoidf_(xl + gl);
            float nv = tanhf_(xc + rv * gch) + lv * xw;
            float hn = (1.f - zv) * hold + zv * nv;
            (pp ? hb1 : hb0)[colg * 32 + r] = hn;
        }
        ++p;
        barrier_arrive(flags, cb, p, tid);
        barrier_wait(flags, p, tid);
        reload_hT(hT, pp ? hb1 : hb0, tid);
        pp ^= 1;
        __syncthreads();

        // ================= 4 transition layers (3 GEMMs = 6 warp jobs) ======
        #pragma unroll 1
        for (int layer = 0; layer < NLAYERS; ++layer) {
            if (w < 6) {
                int mi = w >> 1, kh = w & 1;
                gemm8(hT, Wsm + (4 + layer * 3 + mi) * (HDIM * CPC),
                      Gp + kh * 1024 + mi * 256, kh, lane);
            }
            __syncthreads();
            {
                float hcur = hT[colg * 32 + r];
                float rr = sigmoidf_(Gp[ei]       + Gp[1024 + ei]);
                float zz = sigmoidf_(Gp[256 + ei] + Gp[1280 + ei]);
                float gn =           Gp[512 + ei] + Gp[1536 + ei];
                float nn = tanhf_(rr * gn);
                float hnew = (1.f - zz) * nn + zz * hcur;
                float* hb = pp ? hb1 : hb0;
                if (layer == NLAYERS - 1) {
                    hb[colg * 32 + r] = act ? hnew : hold;
                    if (act)
                        out[((size_t)t * BATCH + b) * HDIM + colg] = hnew;
                } else {
                    hb[colg * 32 + r] = hnew;
                }
            }
            ++p;
            barrier_arrive(flags, cb, p, tid);
            bool last = (layer == NLAYERS - 1) && (t == Lg - 1);
            if (!last) {
                barrier_wait(flags, p, tid);
                reload_hT(hT, pp ? hb1 : hb0, tid);
                pp ^= 1;
                __syncthreads();
            }
        }
    }
}

// ---------------------------------------------------------------------------
// kernel_launch: memset -> x-projection GEMM -> persistent recurrence
// ---------------------------------------------------------------------------
extern "C" void kernel_launch(void* const* d_in, const int* in_sizes, int n_in,
                              void* d_out, int out_size)
{
    const float* x       = (const float*)d_in[0];
    const int*   lengths = (const int*)  d_in[1];
    const float* Wr      = (const float*)d_in[2];
    const float* Wz      = (const float*)d_in[3];
    const float* Wl      = (const float*)d_in[4];
    const float* Wt      = (const float*)d_in[5];
    const float* Cx      = (const float*)d_in[6];
    const float* Ch      = (const float*)d_in[7];
    const float* Tr      = (const float*)d_in[8];
    const float* Tz      = (const float*)d_in[9];
    const float* Tn      = (const float*)d_in[10];
    float* out = (float*)d_out;
    (void)in_sizes; (void)n_in;

    cudaMemsetAsync(out, 0, (size_t)out_size * sizeof(float));

    dim3 ggrid(20, 1024);
    xproj_kernel<<<ggrid, 256>>>(x, Wr, Wz, Wl, Cx, Wt);

    cudaFuncSetAttribute(rnn_kernel,
                         cudaFuncAttributeMaxDynamicSharedMemorySize,
                         SMEM_BYTES);
    rnn_kernel<<<GROUPS * CPG, 256, SMEM_BYTES>>>(
        Wr, Wz, Wl, Ch, Tr, Tz, Tn, lengths, out);
}